// round 17
// baseline (speedup 1.0000x reference)
#include <cuda_runtime.h>
#include <cuda_fp16.h>

#define N_NODES_C 100000
#define E_MAX_C   1600000
#define BN_EPS 1e-5f

// Scratch (device globals — no allocation allowed)
__device__ __half g_q16[(size_t)N_NODES_C * 128];   // x @ W1l^T
__device__ __half g_r16[(size_t)N_NODES_C * 128];   // x @ W1r^T
__device__ __half g_h16[(size_t)N_NODES_C * 128];
__device__ __half g_p16[(size_t)N_NODES_C * 64];
__device__ int    g_deg[N_NODES_C];
__device__ int    g_rowstart[N_NODES_C];   // local-exclusive (within scan block)
__device__ int    g_cursor[N_NODES_C];     // local-exclusive copy for fill
__device__ int    g_blocksum[128];
__device__ int    g_blockoff[128];
__device__ int    g_ticket[1];
__device__ int    g_edge_src[E_MAX_C];

// ---------------------------------------------------------------------------
// Degree histogram (+ticket reset). deg zeroed beforehand via memsetAsync.
__global__ void hist_kernel(const int* __restrict__ ei, int E,
                            int* __restrict__ deg, int* __restrict__ ticket) {
    int e = blockIdx.x * blockDim.x + threadIdx.x;
    if (e == 0) *ticket = 0;
    if (e < E) atomicAdd(&deg[ei[(size_t)E + e]], 1);
}

// Fused scan: per-block scan writes local-exclusive into rowstart AND cursor;
// last block to finish scans the 98 block sums into blockoff.
__global__ void scan12_kernel(const int* __restrict__ deg,
                              int* __restrict__ rowstart,
                              int* __restrict__ cursor,
                              int* __restrict__ blocksum,
                              int* __restrict__ blockoff,
                              int* __restrict__ ticket, int n, int nb) {
    __shared__ int s[1024];
    __shared__ int isLast;
    int tid = threadIdx.x;
    int i = blockIdx.x * 1024 + tid;
    int v = (i < n) ? deg[i] : 0;
    s[tid] = v;
    __syncthreads();
#pragma unroll
    for (int off = 1; off < 1024; off <<= 1) {
        int t = (tid >= off) ? s[tid - off] : 0;
        __syncthreads();
        s[tid] += t;
        __syncthreads();
    }
    if (i < n) {
        int le = s[tid] - v;          // local exclusive
        rowstart[i] = le;
        cursor[i] = le;
    }
    if (tid == 1023) {
        blocksum[blockIdx.x] = s[tid];
        __threadfence();
    }
    __syncthreads();
    if (tid == 0) {
        int old = atomicAdd(ticket, 1);
        isLast = (old == nb - 1);
    }
    __syncthreads();
    if (isLast) {
        __threadfence();
        __shared__ int s2[128];
        int b = (tid < nb) ? ((volatile int*)blocksum)[tid] : 0;
        if (tid < 128) s2[tid] = b;
        __syncthreads();
#pragma unroll
        for (int off = 1; off < 128; off <<= 1) {
            int t = (tid < 128 && tid >= off) ? s2[tid - off] : 0;
            __syncthreads();
            if (tid < 128) s2[tid] += t;
            __syncthreads();
        }
        if (tid < nb) blockoff[tid] = s2[tid] - b;   // exclusive
    }
}

// CSR fill: global position = blockoff[dst>>10] + local cursor bump.
__global__ void fill_kernel(const int* __restrict__ ei, int E,
                            int* __restrict__ cursor,
                            const int* __restrict__ blockoff,
                            int* __restrict__ edge_src) {
    int e = blockIdx.x * blockDim.x + threadIdx.x;
    if (e < E) {
        int src = ei[e];
        int dst = ei[(size_t)E + e];
        int pos = blockoff[dst >> 10] + atomicAdd(&cursor[dst], 1);
        edge_src[pos] = src;
    }
}

// ---------------------------------------------------------------------------
// Pairwise fp16 add of two uint4 payloads (8 halves each): 4 HADD2.
__device__ __forceinline__ uint4 hadd2x4(uint4 a, uint4 b) {
    __half2 r0 = __hadd2(*(__half2*)&a.x, *(__half2*)&b.x);
    __half2 r1 = __hadd2(*(__half2*)&a.y, *(__half2*)&b.y);
    __half2 r2 = __hadd2(*(__half2*)&a.z, *(__half2*)&b.z);
    __half2 r3 = __hadd2(*(__half2*)&a.w, *(__half2*)&b.w);
    uint4 o;
    o.x = *(unsigned*)&r0; o.y = *(unsigned*)&r1;
    o.z = *(unsigned*)&r2; o.w = *(unsigned*)&r3;
    return o;
}

// gather core: LANES lanes per node, fp16 payload, pairwise fp16 pre-add,
// fp32 accumulate. Unroll 8 (MLP 8).
template<int LANES>
__device__ __forceinline__ void gather_core(const uint4* __restrict__ feat16,
                                            const int* __restrict__ rowstart,
                                            const int* __restrict__ blockoff,
                                            const int* __restrict__ deg,
                                            const int* __restrict__ edge_src,
                                            int n, int lane, int& dout,
                                            float acc[8]) {
    int d = deg[n];
    int start = blockoff[n >> 10] + rowstart[n];
    dout = d;
#pragma unroll
    for (int q = 0; q < 8; q++) acc[q] = 0.f;

    auto accum = [&](uint4 u) {
        float2 f0 = __half22float2(*(__half2*)&u.x);
        float2 f1 = __half22float2(*(__half2*)&u.y);
        float2 f2 = __half22float2(*(__half2*)&u.z);
        float2 f3 = __half22float2(*(__half2*)&u.w);
        acc[0] += f0.x; acc[1] += f0.y; acc[2] += f1.x; acc[3] += f1.y;
        acc[4] += f2.x; acc[5] += f2.y; acc[6] += f3.x; acc[7] += f3.y;
    };

    int j = 0;
    for (; j + 7 < d; j += 8) {
        int s0 = edge_src[start + j];
        int s1 = edge_src[start + j + 1];
        int s2 = edge_src[start + j + 2];
        int s3 = edge_src[start + j + 3];
        int s4 = edge_src[start + j + 4];
        int s5 = edge_src[start + j + 5];
        int s6 = edge_src[start + j + 6];
        int s7 = edge_src[start + j + 7];
        uint4 u0 = feat16[(size_t)s0 * LANES + lane];
        uint4 u1 = feat16[(size_t)s1 * LANES + lane];
        uint4 u2 = feat16[(size_t)s2 * LANES + lane];
        uint4 u3 = feat16[(size_t)s3 * LANES + lane];
        uint4 u4 = feat16[(size_t)s4 * LANES + lane];
        uint4 u5 = feat16[(size_t)s5 * LANES + lane];
        uint4 u6 = feat16[(size_t)s6 * LANES + lane];
        uint4 u7 = feat16[(size_t)s7 * LANES + lane];
        accum(hadd2x4(u0, u1));
        accum(hadd2x4(u2, u3));
        accum(hadd2x4(u4, u5));
        accum(hadd2x4(u6, u7));
    }
    for (; j + 1 < d; j += 2) {
        int s0 = edge_src[start + j];
        int s1 = edge_src[start + j + 1];
        uint4 u0 = feat16[(size_t)s0 * LANES + lane];
        uint4 u1 = feat16[(size_t)s1 * LANES + lane];
        accum(hadd2x4(u0, u1));
    }
    if (j < d)
        accum(feat16[(size_t)edge_src[start + j] * LANES + lane]);
}

// Layer-1 gather + BN + ReLU: h16[n] = relu(bn(mean-gather(q16) + r16[n])).
// bias b1l folded into the BN shift.
__global__ void gather_bn_kernel(const uint4* __restrict__ q16,
                                 const uint4* __restrict__ r16,
                                 const int* __restrict__ rowstart,
                                 const int* __restrict__ blockoff,
                                 const int* __restrict__ deg,
                                 const int* __restrict__ edge_src,
                                 const float* __restrict__ bias,
                                 const float* __restrict__ gamma,
                                 const float* __restrict__ beta,
                                 const float* __restrict__ mean,
                                 const float* __restrict__ var,
                                 uint4* __restrict__ h16, int N) {
    constexpr int LANES = 16;
    long long gid = (long long)blockIdx.x * blockDim.x + threadIdx.x;
    int n = (int)(gid / LANES);
    if (n >= N) return;
    int lane = (int)(gid % LANES);
    int d;
    float acc[8];
    gather_core<LANES>(q16, rowstart, blockoff, deg, edge_src, n, lane, d, acc);
    float inv = 1.0f / (float)max(d, 1);

    // own-node r row
    uint4 rr = r16[(size_t)n * LANES + lane];
    float rrow[8];
    {
        float2 f0 = __half22float2(*(__half2*)&rr.x);
        float2 f1 = __half22float2(*(__half2*)&rr.y);
        float2 f2 = __half22float2(*(__half2*)&rr.z);
        float2 f3 = __half22float2(*(__half2*)&rr.w);
        rrow[0] = f0.x; rrow[1] = f0.y; rrow[2] = f1.x; rrow[3] = f1.y;
        rrow[4] = f2.x; rrow[5] = f2.y; rrow[6] = f3.x; rrow[7] = f3.y;
    }

    int cbase = lane * 8;
    float v[8];
#pragma unroll
    for (int q = 0; q < 8; q++) {
        int c = cbase + q;
        float sc = gamma[c] * rsqrtf(var[c] + BN_EPS);
        float sh = beta[c] - mean[c] * sc + bias[c] * sc;
        v[q] = fmaxf((acc[q] * inv + rrow[q]) * sc + sh, 0.f);
    }
    __half2 h0 = __floats2half2_rn(v[0], v[1]);
    __half2 h1 = __floats2half2_rn(v[2], v[3]);
    __half2 h2 = __floats2half2_rn(v[4], v[5]);
    __half2 h3 = __floats2half2_rn(v[6], v[7]);
    uint4 o;
    o.x = *(unsigned*)&h0; o.y = *(unsigned*)&h1;
    o.z = *(unsigned*)&h2; o.w = *(unsigned*)&h3;
    h16[(size_t)n * LANES + lane] = o;
}

// gather (fp16 payload) accumulating into fp32 out
template<int LANES>
__global__ void gather_add32_kernel(const uint4* __restrict__ feat16,
                                    const int* __restrict__ rowstart,
                                    const int* __restrict__ blockoff,
                                    const int* __restrict__ deg,
                                    const int* __restrict__ edge_src,
                                    float* __restrict__ dstbuf, int N) {
    long long gid = (long long)blockIdx.x * blockDim.x + threadIdx.x;
    int n = (int)(gid / LANES);
    if (n >= N) return;
    int lane = (int)(gid % LANES);
    int d;
    float acc[8];
    gather_core<LANES>(feat16, rowstart, blockoff, deg, edge_src, n, lane, d, acc);
    float inv = 1.0f / (float)max(d, 1);
    float* p = dstbuf + (size_t)n * (LANES * 8) + lane * 8;
    float4 o0 = *(float4*)p, o1 = *(float4*)(p + 4);
    o0.x += acc[0] * inv; o0.y += acc[1] * inv;
    o0.z += acc[2] * inv; o0.w += acc[3] * inv;
    o1.x += acc[4] * inv; o1.y += acc[5] * inv;
    o1.z += acc[6] * inv; o1.w += acc[7] * inv;
    *(float4*)p = o0; *(float4*)(p + 4) = o1;
}

// ---------------------------------------------------------------------------
// fp16 tensor-core GEMM (m16n8k16, fp32 accumulate).
// Block 128x128, 8 warps (4M x 2N), warp tile 32x64, BK=32 halves.
// Smem stride 40 halves: fragment half2 load bank = (20g+t) mod 32 — conflict-free.
#define ASTRH 40

__device__ __forceinline__ void mma16n8k16(float* c, const unsigned* a,
                                           const unsigned* b) {
    asm volatile(
        "mma.sync.aligned.m16n8k16.row.col.f32.f16.f16.f32 "
        "{%0,%1,%2,%3}, {%4,%5,%6,%7}, {%8,%9}, {%0,%1,%2,%3};"
        : "+f"(c[0]), "+f"(c[1]), "+f"(c[2]), "+f"(c[3])
        : "r"(a[0]), "r"(a[1]), "r"(a[2]), "r"(a[3]), "r"(b[0]), "r"(b[1]));
}

__device__ __forceinline__ void mma_tile16(const __half* As, const __half* Ws,
                                           int wm, int wn, int g, int t,
                                           float c[2][8][4]) {
#pragma unroll
    for (int kc = 0; kc < 2; ++kc) {
        unsigned afr[2][4];
#pragma unroll
        for (int m = 0; m < 2; m++) {
            int r0 = wm * 32 + m * 16 + g;
            afr[m][0] = *(const unsigned*)&As[r0 * ASTRH + kc * 16 + 2 * t];
            afr[m][1] = *(const unsigned*)&As[(r0 + 8) * ASTRH + kc * 16 + 2 * t];
            afr[m][2] = *(const unsigned*)&As[r0 * ASTRH + kc * 16 + 8 + 2 * t];
            afr[m][3] = *(const unsigned*)&As[(r0 + 8) * ASTRH + kc * 16 + 8 + 2 * t];
        }
#pragma unroll
        for (int nt = 0; nt < 8; nt++) {
            int nrow = wn * 64 + nt * 8 + g;
            unsigned bfr[2] = {
                *(const unsigned*)&Ws[nrow * ASTRH + kc * 16 + 2 * t],
                *(const unsigned*)&Ws[nrow * ASTRH + kc * 16 + 8 + 2 * t]};
            mma16n8k16(c[0][nt], afr[0], bfr);
            mma16n8k16(c[1][nt], afr[1], bfr);
        }
    }
}

// GEMM0: from x (fp32, K=128) produce q16 = x@W1l^T (grid.y=0) or
// r16 = x@W1r^T (grid.y=1). No bias, no epilogue — folded into gather_bn.
__global__ __launch_bounds__(256)
void gemm0_f16(const float* __restrict__ x,
               const float* __restrict__ W1l,
               const float* __restrict__ W1r,
               __half* __restrict__ q16,
               __half* __restrict__ r16, int N) {
    __shared__ __half As[128 * ASTRH];
    __shared__ __half Ws[128 * ASTRH];
    const int tid = threadIdx.x;
    const int lane = tid & 31, warp = tid >> 5;
    const int wm = warp & 3, wn = warp >> 2;
    const int g = lane >> 2, t = lane & 3;
    const int blockRow = blockIdx.x * 128;
    const float* W = (blockIdx.y == 0) ? W1l : W1r;
    __half* outp = (blockIdx.y == 0) ? q16 : r16;
    const int row4 = tid >> 1;                  // shared by 2 threads? no:
    // loads: 1024 float4 per tile per matrix; 4 per thread.
    const int lrow = tid >> 3, lq = tid & 7;    // row slot (32 rows/pass), q4 0..7

    float c[2][8][4];
#pragma unroll
    for (int m = 0; m < 2; m++)
#pragma unroll
        for (int nt = 0; nt < 8; nt++)
#pragma unroll
            for (int q = 0; q < 4; q++) c[m][nt][q] = 0.f;

    float4 vx[4], vw[4];
    auto loadRegs = [&](int kt) {
        const int kloc = kt * 32;
#pragma unroll
        for (int p = 0; p < 4; ++p) {
            int row = lrow + p * 32;
            int n = blockRow + row;
            vx[p] = make_float4(0.f, 0.f, 0.f, 0.f);
            if (n < N) vx[p] = *(const float4*)(x + (size_t)n * 128 + kloc + lq * 4);
            vw[p] = *(const float4*)(W + (size_t)row * 128 + kloc + lq * 4);
        }
    };
    auto storeSmem = [&]() {
#pragma unroll
        for (int p = 0; p < 4; ++p) {
            int row = lrow + p * 32;
            __half2 alo = __floats2half2_rn(vx[p].x, vx[p].y);
            __half2 ahi = __floats2half2_rn(vx[p].z, vx[p].w);
            *(uint2*)&As[row * ASTRH + lq * 4] =
                make_uint2(*(unsigned*)&alo, *(unsigned*)&ahi);
            __half2 wlo = __floats2half2_rn(vw[p].x, vw[p].y);
            __half2 whi = __floats2half2_rn(vw[p].z, vw[p].w);
            *(uint2*)&Ws[row * ASTRH + lq * 4] =
                make_uint2(*(unsigned*)&wlo, *(unsigned*)&whi);
        }
    };

    loadRegs(0);
    storeSmem();
    __syncthreads();
    for (int kt = 0; kt < 4; ++kt) {
        if (kt < 3) loadRegs(kt + 1);
        mma_tile16(As, Ws, wm, wn, g, t, c);
        __syncthreads();
        if (kt < 3) {
            storeSmem();
            __syncthreads();
        }
    }

#pragma unroll
    for (int nt = 0; nt < 8; nt++) {
        int col0 = wn * 64 + nt * 8 + 2 * t;
#pragma unroll
        for (int m = 0; m < 2; m++) {
            int r = blockRow + wm * 32 + m * 16 + g;
            if (r < N) {
                __half2 v = __floats2half2_rn(c[m][nt][0], c[m][nt][1]);
                *(__half2*)(outp + (size_t)r * 128 + col0) = v;
            }
            int r2 = r + 8;
            if (r2 < N) {
                __half2 v = __floats2half2_rn(c[m][nt][2], c[m][nt][3]);
                *(__half2*)(outp + (size_t)r2 * 128 + col0) = v;
            }
        }
    }
}

// GEMM2: K=128; wn==0 -> p16 = fp16(h@W2l^T); wn==1 -> out = h@W2r^T + b2l
__global__ __launch_bounds__(256)
void gemm2_f16(const __half* __restrict__ h16,
               const float* __restrict__ W2l,
               const float* __restrict__ W2r,
               const float* __restrict__ b2l,
               __half* __restrict__ p16,
               float* __restrict__ out, int N) {
    __shared__ __half As[128 * ASTRH];
    __shared__ __half Ws[128 * ASTRH];
    const int tid = threadIdx.x;
    const int lane = tid & 31, warp = tid >> 5;
    const int wm = warp & 3, wn = warp >> 2;
    const int g = lane >> 2, t = lane & 3;
    const int blockRow = blockIdx.x * 128;
    const int arow = tid >> 2, aq = tid & 3;
    const int wrow = tid >> 3, wq = tid & 7;

    float c[2][8][4];
#pragma unroll
    for (int m = 0; m < 2; m++)
#pragma unroll
        for (int nt = 0; nt < 8; nt++)
#pragma unroll
            for (int q = 0; q < 4; q++) c[m][nt][q] = 0.f;

    uint4 va[2];
    float4 vw[4];
    auto loadRegs = [&](int kt) {
        const int kloc = kt * 32;
#pragma unroll
        for (int p = 0; p < 2; ++p) {
            int row = arow + p * 64;
            int n = blockRow + row;
            va[p] = make_uint4(0, 0, 0, 0);
            if (n < N)
                va[p] = *(const uint4*)(h16 + (size_t)n * 128 + kloc + aq * 8);
        }
#pragma unroll
        for (int p = 0; p < 4; ++p) {
            int row = wrow + p * 32;
            const float* Wsrc = (row < 64) ? (W2l + (size_t)row * 128)
                                           : (W2r + (size_t)(row - 64) * 128);
            vw[p] = *(const float4*)(Wsrc + kloc + wq * 4);
        }
    };
    auto storeSmem = [&]() {
#pragma unroll
        for (int p = 0; p < 2; ++p) {
            int row = arow + p * 64;
            *(uint4*)&As[row * ASTRH + aq * 8] = va[p];
        }
#pragma unroll
        for (int p = 0; p < 4; ++p) {
            int row = wrow + p * 32;
            __half2 lo = __floats2half2_rn(vw[p].x, vw[p].y);
            __half2 hi = __floats2half2_rn(vw[p].z, vw[p].w);
            uint2 u = make_uint2(*(unsigned*)&lo, *(unsigned*)&hi);
            *(uint2*)&Ws[row * ASTRH + wq * 4] = u;
        }
    };

    loadRegs(0);
    storeSmem();
    __syncthreads();
    for (int kt = 0; kt < 4; ++kt) {
        if (kt < 3) loadRegs(kt + 1);
        mma_tile16(As, Ws, wm, wn, g, t, c);
        __syncthreads();
        if (kt < 3) {
            storeSmem();
            __syncthreads();
        }
    }

    if (wn == 0) {   // p16, cols 0..63, no bias
#pragma unroll
        for (int nt = 0; nt < 8; nt++) {
            int col0 = nt * 8 + 2 * t;
#pragma unroll
            for (int m = 0; m < 2; m++) {
                int r = blockRow + wm * 32 + m * 16 + g;
                if (r < N) {
                    __half2 v = __floats2half2_rn(c[m][nt][0], c[m][nt][1]);
                    *(__half2*)(p16 + (size_t)r * 64 + col0) = v;
                }
                int r2 = r + 8;
                if (r2 < N) {
                    __half2 v = __floats2half2_rn(c[m][nt][2], c[m][nt][3]);
                    *(__half2*)(p16 + (size_t)r2 * 64 + col0) = v;
                }
            }
        }
    } else {         // out, + bias
#pragma unroll
        for (int nt = 0; nt < 8; nt++) {
            int col0 = nt * 8 + 2 * t;
            float b0 = b2l[col0], b1 = b2l[col0 + 1];
#pragma unroll
            for (int m = 0; m < 2; m++) {
                int r = blockRow + wm * 32 + m * 16 + g;
                if (r < N)
                    *(float2*)(out + (size_t)r * 64 + col0) =
                        make_float2(c[m][nt][0] + b0, c[m][nt][1] + b1);
                int r2 = r + 8;
                if (r2 < N)
                    *(float2*)(out + (size_t)r2 * 64 + col0) =
                        make_float2(c[m][nt][2] + b0, c[m][nt][3] + b1);
            }
        }
    }
}

// ---------------------------------------------------------------------------
extern "C" void kernel_launch(void* const* d_in, const int* in_sizes, int n_in,
                              void* d_out, int out_size) {
    const float* x        = (const float*)d_in[0];
    const int* ei         = (const int*)d_in[1];   // int32 (JAX x64 disabled)
    const float* W1l      = (const float*)d_in[2];
    const float* b1l      = (const float*)d_in[3];
    const float* W1r      = (const float*)d_in[4];
    const float* bn_gamma = (const float*)d_in[5];
    const float* bn_beta  = (const float*)d_in[6];
    const float* bn_mean  = (const float*)d_in[7];
    const float* bn_var   = (const float*)d_in[8];
    const float* W2l      = (const float*)d_in[9];
    const float* b2l      = (const float*)d_in[10];
    const float* W2r      = (const float*)d_in[11];
    float* out            = (float*)d_out;

    const int N = N_NODES_C;
    const int E = in_sizes[1] / 2;

    __half *q16, *r16, *h16, *p16;
    int *deg, *rowstart, *cursor, *blocksum, *blockoff, *ticket, *edge_src;
    cudaGetSymbolAddress((void**)&q16, g_q16);
    cudaGetSymbolAddress((void**)&r16, g_r16);
    cudaGetSymbolAddress((void**)&h16, g_h16);
    cudaGetSymbolAddress((void**)&p16, g_p16);
    cudaGetSymbolAddress((void**)&deg, g_deg);
    cudaGetSymbolAddress((void**)&rowstart, g_rowstart);
    cudaGetSymbolAddress((void**)&cursor, g_cursor);
    cudaGetSymbolAddress((void**)&blocksum, g_blocksum);
    cudaGetSymbolAddress((void**)&blockoff, g_blockoff);
    cudaGetSymbolAddress((void**)&ticket, g_ticket);
    cudaGetSymbolAddress((void**)&edge_src, g_edge_src);

    const int nb = (N + 1023) / 1024;   // 98 scan blocks

    // One-time side stream + fork/join events (host-side resources only).
    static cudaStream_t s2 = nullptr;
    static cudaEvent_t evFork = nullptr, evJoin = nullptr;
    if (s2 == nullptr) {
        cudaStreamCreateWithFlags(&s2, cudaStreamNonBlocking);
        cudaEventCreateWithFlags(&evFork, cudaEventDisableTiming);
        cudaEventCreateWithFlags(&evJoin, cudaEventDisableTiming);
    }

    // Fork: gemm0 (q16, r16) depends only on inputs -> run on s2 concurrent
    // with the CSR build on the main stream.
    cudaEventRecord(evFork, 0);
    cudaStreamWaitEvent(s2, evFork, 0);
    {
        dim3 grid((N + 127) / 128, 2);
        gemm0_f16<<<grid, 256, 0, s2>>>(x, W1l, W1r, q16, r16, N);
    }
    cudaEventRecord(evJoin, s2);

    // Main stream: CSR build
    cudaMemsetAsync(deg, 0, N * sizeof(int));
    hist_kernel<<<(E + 255) / 256, 256>>>(ei, E, deg, ticket);
    scan12_kernel<<<nb, 1024>>>(deg, rowstart, cursor, blocksum, blockoff,
                                ticket, N, nb);
    fill_kernel<<<(E + 255) / 256, 256>>>(ei, E, cursor, blockoff, edge_src);

    // Join: gather_bn needs q16/r16 + CSR
    cudaStreamWaitEvent(0, evJoin, 0);

    // Layer 1: h16 = relu(bn(mean-gather(q16) + r16))
    {
        long long threads = (long long)N * 16;
        gather_bn_kernel<<<(int)((threads + 255) / 256), 256>>>(
            (const uint4*)q16, (const uint4*)r16, rowstart, blockoff, deg,
            edge_src, b1l, bn_gamma, bn_beta, bn_mean, bn_var,
            (uint4*)h16, N);
    }
    // Layer 2: p16 = fp16(h@W2l^T); out = h@W2r^T + b2l
    gemm2_f16<<<(N + 127) / 128, 256>>>(h16, W2l, W2r, b2l, p16, out, N);
    // out += mean-gather(p16)
    {
        long long threads = (long long)N * 8;
        gather_add32_kernel<8><<<(int)((threads + 255) / 256), 256>>>(
            (const uint4*)p16, rowstart, blockoff, deg, edge_src, out, N);
    }
}